// round 6
// baseline (speedup 1.0000x reference)
#include <cuda_runtime.h>
#include <cstdint>
#include <cstddef>

#define B_ 8192
#define N_ 512

// branchless fp32 cyclic Jacobi rotation on symmetric 3x3 (fast-path math)
#define JROT(app, aqq, apq, arp, arq, vAp, vAq, vBp, vBq, vCp, vCq) do {      \
    float _a = (apq);                                                          \
    float _as = fabsf(_a) > 1e-20f ? _a : 1e-20f;                              \
    float _th = __fdividef(0.5f * ((aqq) - (app)), _as);                       \
    float _t = copysignf(1.f, _th) / (fabsf(_th) + sqrtf(fmaf(_th, _th, 1.f)));\
    float _c = rsqrtf(fmaf(_t, _t, 1.f));                                      \
    float _s = _t * _c;                                                        \
    (app) -= _t * _a; (aqq) += _t * _a; (apq) = 0.f;                           \
    float _rp = (arp), _rq = (arq);                                            \
    (arp) = _c * _rp - _s * _rq; (arq) = _s * _rp + _c * _rq;                  \
    float _x;                                                                  \
    _x = (vAp); (vAp) = _c * _x - _s * (vAq); (vAq) = _s * _x + _c * (vAq);    \
    _x = (vBp); (vBp) = _c * _x - _s * (vBq); (vBq) = _s * _x + _c * (vBq);    \
    _x = (vCp); (vCp) = _c * _x - _s * (vCq); (vCq) = _s * _x + _c * (vCq);    \
} while (0)

// ---------------------------------------------------------------------------
// Fully fused: block = batch. Reduce moments -> thread0 fp32 SVD -> apply.
// ---------------------------------------------------------------------------
__global__ __launch_bounds__(128) void k_fused(
    const float* __restrict__ pred, const float* __restrict__ truc,
    const float* __restrict__ wgt, const unsigned int* __restrict__ msk,
    float* __restrict__ out)
{
    int b = blockIdx.x, tid = threadIdx.x;

    const float4* tp = reinterpret_cast<const float4*>(truc + (size_t)b * 1536) + tid * 3;
    const float4* pp = reinterpret_cast<const float4*>(pred + (size_t)b * 1536) + tid * 3;

    float4 tv0 = tp[0], tv1 = tp[1], tv2 = tp[2];
    float4 pv0 = pp[0], pv1 = pp[1], pv2 = pp[2];
    float4 wv4 = reinterpret_cast<const float4*>(wgt + (size_t)b * 512)[tid];
    uint4  mv  = reinterpret_cast<const uint4*>(msk + (size_t)b * 512)[tid];

    float ta[12] = { tv0.x, tv0.y, tv0.z, tv0.w, tv1.x, tv1.y, tv1.z, tv1.w,
                     tv2.x, tv2.y, tv2.z, tv2.w };
    float pa[12] = { pv0.x, pv0.y, pv0.z, pv0.w, pv1.x, pv1.y, pv1.z, pv1.w,
                     pv2.x, pv2.y, pv2.z, pv2.w };
    float wa[4]  = { wv4.x, wv4.y, wv4.z, wv4.w };
    unsigned int ma[4] = { mv.x, mv.y, mv.z, mv.w };

    float acc[16];
#pragma unroll
    for (int k = 0; k < 16; k++) acc[k] = 0.f;
    unsigned int m4 = 0;

#pragma unroll
    for (int k = 0; k < 4; k++) {
        unsigned int on = (ma[k] != 0u);
        m4 |= on << k;
        float w = on ? wa[k] : 0.f;
        float tx = ta[3 * k], ty = ta[3 * k + 1], tz = ta[3 * k + 2];
        float px = pa[3 * k], py = pa[3 * k + 1], pz = pa[3 * k + 2];
        float wtx = w * tx, wty = w * ty, wtz = w * tz;
        acc[0] = fmaf(wtx, px, acc[0]); acc[1] = fmaf(wtx, py, acc[1]); acc[2] = fmaf(wtx, pz, acc[2]);
        acc[3] = fmaf(wty, px, acc[3]); acc[4] = fmaf(wty, py, acc[4]); acc[5] = fmaf(wty, pz, acc[5]);
        acc[6] = fmaf(wtz, px, acc[6]); acc[7] = fmaf(wtz, py, acc[7]); acc[8] = fmaf(wtz, pz, acc[8]);
        acc[9] += wtx; acc[10] += wty; acc[11] += wtz;
        acc[12] = fmaf(w, px, acc[12]); acc[13] = fmaf(w, py, acc[13]); acc[14] = fmaf(w, pz, acc[14]);
        acc[15] += w;
    }

#pragma unroll
    for (int k = 0; k < 16; k++) {
#pragma unroll
        for (int o = 16; o > 0; o >>= 1)
            acc[k] += __shfl_xor_sync(0xFFFFFFFFu, acc[k], o);
    }

    __shared__ float sred[4][16];
    __shared__ float srt[12];
    int wid = tid >> 5, lane = tid & 31;
    if (lane == 0) {
#pragma unroll
        for (int k = 0; k < 16; k++) sred[wid][k] = acc[k];
    }
    __syncthreads();

    if (tid == 0) {
        float r[16];
#pragma unroll
        for (int k = 0; k < 16; k++)
            r[k] = sred[0][k] + sred[1][k] + sred[2][k] + sred[3][k];

        float inv = __fdividef(1.f, r[15]);
        float c0 = r[9] * inv, c1 = r[10] * inv, c2 = r[11] * inv;

        float cov[9];
#pragma unroll
        for (int i = 0; i < 3; i++)
#pragma unroll
            for (int j = 0; j < 3; j++)
                cov[i * 3 + j] = r[i * 3 + j] - r[9 + i] * r[12 + j] * inv;

        // det sign in fp64 EARLY: runs on the fp64 pipe concurrently with the
        // fp32 Jacobi chain below (independent).
        double det = (double)cov[0] * ((double)cov[4] * cov[8] - (double)cov[5] * cov[7])
                   - (double)cov[1] * ((double)cov[3] * cov[8] - (double)cov[5] * cov[6])
                   + (double)cov[2] * ((double)cov[3] * cov[7] - (double)cov[4] * cov[6]);

        // M = cov^T cov (symmetric)
        float m00 = 0, m01 = 0, m02 = 0, m11 = 0, m12 = 0, m22 = 0;
#pragma unroll
        for (int k = 0; k < 3; k++) {
            float a0 = cov[k * 3], a1 = cov[k * 3 + 1], a2 = cov[k * 3 + 2];
            m00 = fmaf(a0, a0, m00); m01 = fmaf(a0, a1, m01); m02 = fmaf(a0, a2, m02);
            m11 = fmaf(a1, a1, m11); m12 = fmaf(a1, a2, m12); m22 = fmaf(a2, a2, m22);
        }

        float v00 = 1, v01 = 0, v02 = 0, v10 = 0, v11 = 1, v12 = 0, v20 = 0, v21 = 0, v22 = 1;
#pragma unroll
        for (int sweep = 0; sweep < 4; sweep++) {
            JROT(m00, m11, m01, m02, m12, v00, v01, v10, v11, v20, v21);
            JROT(m00, m22, m02, m01, m12, v00, v02, v10, v12, v20, v22);
            JROT(m11, m22, m12, m01, m02, v01, v02, v11, v12, v21, v22);
        }

        int imin = 0; float lmin = m00;
        if (m11 < lmin) { lmin = m11; imin = 1; }
        if (m22 < lmin) { lmin = m22; imin = 2; }
        int ia = (imin == 0) ? 1 : 0;
        int ib = (imin == 2) ? 1 : 2;

        float vd[9] = { v00, v01, v02, v10, v11, v12, v20, v21, v22 }; // col = eigvec

        // rebuild smallest-sigma direction as cross of the dominant two
        {
            float ax = vd[ia], ay = vd[3 + ia], az = vd[6 + ia];
            float bx = vd[ib], by = vd[3 + ib], bz = vd[6 + ib];
            float cx = ay * bz - az * by;
            float cy = az * bx - ax * bz;
            float cz = ax * by - ay * bx;
            float inm = rsqrtf(fmaf(cx, cx, fmaf(cy, cy, cz * cz)));
            vd[imin] = cx * inm; vd[3 + imin] = cy * inm; vd[6 + imin] = cz * inm;
        }

        float rot[9] = { 0, 0, 0, 0, 0, 0, 0, 0, 0 };
#pragma unroll
        for (int i = 0; i < 3; i++) {
            float vx = vd[i], vy = vd[3 + i], vz = vd[6 + i];
            float g0 = cov[0] * vx + cov[1] * vy + cov[2] * vz;
            float g1 = cov[3] * vx + cov[4] * vy + cov[5] * vz;
            float g2 = cov[6] * vx + cov[7] * vy + cov[8] * vz;
            float coef = rsqrtf(fmaf(g0, g0, fmaf(g1, g1, g2 * g2)));
            if (i == imin && det < 0.0) coef = -coef;
            rot[0] = fmaf(coef * vx, g0, rot[0]); rot[1] = fmaf(coef * vx, g1, rot[1]); rot[2] = fmaf(coef * vx, g2, rot[2]);
            rot[3] = fmaf(coef * vy, g0, rot[3]); rot[4] = fmaf(coef * vy, g1, rot[4]); rot[5] = fmaf(coef * vy, g2, rot[5]);
            rot[6] = fmaf(coef * vz, g0, rot[6]); rot[7] = fmaf(coef * vz, g1, rot[7]); rot[8] = fmaf(coef * vz, g2, rot[8]);
        }

#pragma unroll
        for (int k = 0; k < 9; k++) srt[k] = rot[k];
        srt[9] = c0; srt[10] = c1; srt[11] = c2;
    }
    __syncthreads();

    float r00 = srt[0], r01 = srt[1], r02 = srt[2];
    float r10 = srt[3], r11 = srt[4], r12 = srt[5];
    float r20 = srt[6], r21 = srt[7], r22 = srt[8];
    float c0 = srt[9], c1 = srt[10], c2 = srt[11];

    float4 ov[3];
    float* oa = reinterpret_cast<float*>(ov);
#pragma unroll
    for (int k = 0; k < 4; k++) {
        float m = (m4 >> k) & 1u ? 1.f : 0.f;
        float x = ta[3 * k] * m - c0;
        float y = ta[3 * k + 1] * m - c1;
        float z = ta[3 * k + 2] * m - c2;
        oa[3 * k + 0] = fmaf(r00, x, fmaf(r01, y, fmaf(r02, z, c0)));
        oa[3 * k + 1] = fmaf(r10, x, fmaf(r11, y, fmaf(r12, z, c1)));
        oa[3 * k + 2] = fmaf(r20, x, fmaf(r21, y, fmaf(r22, z, c2)));
    }

    float4* op = reinterpret_cast<float4*>(out + (size_t)b * 1536) + tid * 3;
    op[0] = ov[0]; op[1] = ov[1]; op[2] = ov[2];
}

// ---------------------------------------------------------------------------
extern "C" void kernel_launch(void* const* d_in, const int* in_sizes, int n_in,
                              void* d_out, int out_size)
{
    const float* pred = (const float*)d_in[0];
    const float* truc = (const float*)d_in[1];
    const float* wgt  = (const float*)d_in[2];
    const unsigned int* msk = (const unsigned int*)d_in[3];
    float* out = (float*)d_out;

    k_fused<<<B_, 128>>>(pred, truc, wgt, msk, out);
}

// round 7
// speedup vs baseline: 1.0511x; 1.0511x over previous
#include <cuda_runtime.h>
#include <cstdint>
#include <cstddef>

#define B_ 8192
#define N_ 512

// fp32 cyclic Jacobi rotation on symmetric 3x3 (branchy: skips converged)
#define JROT(app, aqq, apq, arp, arq, vAp, vAq, vBp, vBq, vCp, vCq) do {      \
    float _a = (apq);                                                          \
    if (fabsf(_a) > 1e-12f * (fabsf(app) + fabsf(aqq))) {                      \
        float _th = 0.5f * ((aqq) - (app)) / _a;                               \
        float _t = copysignf(1.f, _th) / (fabsf(_th) + sqrtf(fmaf(_th, _th, 1.f))); \
        float _c = rsqrtf(fmaf(_t, _t, 1.f));                                  \
        float _s = _t * _c;                                                    \
        (app) -= _t * _a; (aqq) += _t * _a; (apq) = 0.f;                       \
        float _rp = (arp), _rq = (arq);                                        \
        (arp) = _c * _rp - _s * _rq; (arq) = _s * _rp + _c * _rq;              \
        float _x;                                                              \
        _x = (vAp); (vAp) = _c * _x - _s * (vAq); (vAq) = _s * _x + _c * (vAq);\
        _x = (vBp); (vBp) = _c * _x - _s * (vBq); (vBq) = _s * _x + _c * (vBq);\
        _x = (vCp); (vCp) = _c * _x - _s * (vCq); (vCq) = _s * _x + _c * (vCq);\
    } } while (0)

__device__ __forceinline__ float frsqrt(float x) {
    float y = rsqrtf(x);
    return y * (1.5f - (0.5f * x) * y * y);
}

// ---------------------------------------------------------------------------
// Fused, 2 batches per 256-thread block. Each 128-thread group handles one
// batch; the two per-batch SVDs run concurrently (threads 0 and 128 live in
// different warps), so one barrier bubble covers 2 batches of streaming.
// ---------------------------------------------------------------------------
__global__ __launch_bounds__(256) void k_fused(
    const float* __restrict__ pred, const float* __restrict__ truc,
    const float* __restrict__ wgt, const unsigned int* __restrict__ msk,
    float* __restrict__ out)
{
    int g   = threadIdx.x >> 7;        // batch slot in block (0/1)
    int t   = threadIdx.x & 127;       // thread within batch group
    int b   = blockIdx.x * 2 + g;

    const float4* tp = reinterpret_cast<const float4*>(truc + (size_t)b * 1536) + t * 3;
    const float4* pp = reinterpret_cast<const float4*>(pred + (size_t)b * 1536) + t * 3;

    float4 tv0 = tp[0], tv1 = tp[1], tv2 = tp[2];
    float4 pv0 = pp[0], pv1 = pp[1], pv2 = pp[2];
    float4 wv4 = reinterpret_cast<const float4*>(wgt + (size_t)b * 512)[t];
    uint4  mv  = reinterpret_cast<const uint4*>(msk + (size_t)b * 512)[t];

    float ta[12] = { tv0.x, tv0.y, tv0.z, tv0.w, tv1.x, tv1.y, tv1.z, tv1.w,
                     tv2.x, tv2.y, tv2.z, tv2.w };
    float pa[12] = { pv0.x, pv0.y, pv0.z, pv0.w, pv1.x, pv1.y, pv1.z, pv1.w,
                     pv2.x, pv2.y, pv2.z, pv2.w };
    float wa[4]  = { wv4.x, wv4.y, wv4.z, wv4.w };
    unsigned int ma[4] = { mv.x, mv.y, mv.z, mv.w };

    float acc[16];
#pragma unroll
    for (int k = 0; k < 16; k++) acc[k] = 0.f;
    unsigned int m4 = 0;

#pragma unroll
    for (int k = 0; k < 4; k++) {
        unsigned int on = (ma[k] != 0u);
        m4 |= on << k;
        float w = on ? wa[k] : 0.f;
        float tx = ta[3 * k], ty = ta[3 * k + 1], tz = ta[3 * k + 2];
        float px = pa[3 * k], py = pa[3 * k + 1], pz = pa[3 * k + 2];
        float wtx = w * tx, wty = w * ty, wtz = w * tz;
        acc[0] = fmaf(wtx, px, acc[0]); acc[1] = fmaf(wtx, py, acc[1]); acc[2] = fmaf(wtx, pz, acc[2]);
        acc[3] = fmaf(wty, px, acc[3]); acc[4] = fmaf(wty, py, acc[4]); acc[5] = fmaf(wty, pz, acc[5]);
        acc[6] = fmaf(wtz, px, acc[6]); acc[7] = fmaf(wtz, py, acc[7]); acc[8] = fmaf(wtz, pz, acc[8]);
        acc[9] += wtx; acc[10] += wty; acc[11] += wtz;
        acc[12] = fmaf(w, px, acc[12]); acc[13] = fmaf(w, py, acc[13]); acc[14] = fmaf(w, pz, acc[14]);
        acc[15] += w;
    }

#pragma unroll
    for (int k = 0; k < 16; k++) {
#pragma unroll
        for (int o = 16; o > 0; o >>= 1)
            acc[k] += __shfl_xor_sync(0xFFFFFFFFu, acc[k], o);
    }

    __shared__ float sred[2][4][16];
    __shared__ float srt[2][12];
    int wid = t >> 5, lane = threadIdx.x & 31;
    if (lane == 0) {
#pragma unroll
        for (int k = 0; k < 16; k++) sred[g][wid][k] = acc[k];
    }
    __syncthreads();

    if (t == 0) {   // threads 0 and 128: two SVDs run concurrently
        float r[16];
#pragma unroll
        for (int k = 0; k < 16; k++)
            r[k] = sred[g][0][k] + sred[g][1][k] + sred[g][2][k] + sred[g][3][k];

        float inv = 1.f / r[15];
        float c0 = r[9] * inv, c1 = r[10] * inv, c2 = r[11] * inv;

        float cov[9];
#pragma unroll
        for (int i = 0; i < 3; i++)
#pragma unroll
            for (int j = 0; j < 3; j++)
                cov[i * 3 + j] = r[i * 3 + j] - r[9 + i] * r[12 + j] * inv;

        // M = cov^T cov (symmetric)
        float m00 = 0, m01 = 0, m02 = 0, m11 = 0, m12 = 0, m22 = 0;
#pragma unroll
        for (int k = 0; k < 3; k++) {
            float a0 = cov[k * 3], a1 = cov[k * 3 + 1], a2 = cov[k * 3 + 2];
            m00 = fmaf(a0, a0, m00); m01 = fmaf(a0, a1, m01); m02 = fmaf(a0, a2, m02);
            m11 = fmaf(a1, a1, m11); m12 = fmaf(a1, a2, m12); m22 = fmaf(a2, a2, m22);
        }

        float v00 = 1, v01 = 0, v02 = 0, v10 = 0, v11 = 1, v12 = 0, v20 = 0, v21 = 0, v22 = 1;
#pragma unroll
        for (int sweep = 0; sweep < 5; sweep++) {
            JROT(m00, m11, m01, m02, m12, v00, v01, v10, v11, v20, v21);
            JROT(m00, m22, m02, m01, m12, v00, v02, v10, v12, v20, v22);
            JROT(m11, m22, m12, m01, m02, v01, v02, v11, v12, v21, v22);
        }

        int imin = 0; float lmin = m00;
        if (m11 < lmin) { lmin = m11; imin = 1; }
        if (m22 < lmin) { lmin = m22; imin = 2; }
        int ia = (imin == 0) ? 1 : 0;
        int ib = (imin == 2) ? 1 : 2;

        float vd[9] = { v00, v01, v02, v10, v11, v12, v20, v21, v22 }; // col = eigvec

        // rebuild smallest-sigma direction as cross of the dominant two
        {
            float ax = vd[ia], ay = vd[3 + ia], az = vd[6 + ia];
            float bx = vd[ib], by = vd[3 + ib], bz = vd[6 + ib];
            float cx = ay * bz - az * by;
            float cy = az * bx - ax * bz;
            float cz = ax * by - ay * bx;
            float inm = frsqrt(cx * cx + cy * cy + cz * cz);
            vd[imin] = cx * inm; vd[3 + imin] = cy * inm; vd[6 + imin] = cz * inm;
        }

        // det sign (fp64, short chain, after Jacobi so doubles aren't live long)
        double det = (double)cov[0] * ((double)cov[4] * cov[8] - (double)cov[5] * cov[7])
                   - (double)cov[1] * ((double)cov[3] * cov[8] - (double)cov[5] * cov[6])
                   + (double)cov[2] * ((double)cov[3] * cov[7] - (double)cov[4] * cov[6]);

        float rot[9] = { 0, 0, 0, 0, 0, 0, 0, 0, 0 };
#pragma unroll
        for (int i = 0; i < 3; i++) {
            float vx = vd[i], vy = vd[3 + i], vz = vd[6 + i];
            float g0 = cov[0] * vx + cov[1] * vy + cov[2] * vz;
            float g1 = cov[3] * vx + cov[4] * vy + cov[5] * vz;
            float g2 = cov[6] * vx + cov[7] * vy + cov[8] * vz;
            float coef = frsqrt(fmaf(g0, g0, fmaf(g1, g1, g2 * g2)));
            if (i == imin && det < 0.0) coef = -coef;
            rot[0] = fmaf(coef * vx, g0, rot[0]); rot[1] = fmaf(coef * vx, g1, rot[1]); rot[2] = fmaf(coef * vx, g2, rot[2]);
            rot[3] = fmaf(coef * vy, g0, rot[3]); rot[4] = fmaf(coef * vy, g1, rot[4]); rot[5] = fmaf(coef * vy, g2, rot[5]);
            rot[6] = fmaf(coef * vz, g0, rot[6]); rot[7] = fmaf(coef * vz, g1, rot[7]); rot[8] = fmaf(coef * vz, g2, rot[8]);
        }

#pragma unroll
        for (int k = 0; k < 9; k++) srt[g][k] = rot[k];
        srt[g][9] = c0; srt[g][10] = c1; srt[g][11] = c2;
    }
    __syncthreads();

    float r00 = srt[g][0], r01 = srt[g][1], r02 = srt[g][2];
    float r10 = srt[g][3], r11 = srt[g][4], r12 = srt[g][5];
    float r20 = srt[g][6], r21 = srt[g][7], r22 = srt[g][8];
    float c0 = srt[g][9], c1 = srt[g][10], c2 = srt[g][11];

    float4 ov[3];
    float* oa = reinterpret_cast<float*>(ov);
#pragma unroll
    for (int k = 0; k < 4; k++) {
        float m = (m4 >> k) & 1u ? 1.f : 0.f;
        float x = ta[3 * k] * m - c0;
        float y = ta[3 * k + 1] * m - c1;
        float z = ta[3 * k + 2] * m - c2;
        oa[3 * k + 0] = fmaf(r00, x, fmaf(r01, y, fmaf(r02, z, c0)));
        oa[3 * k + 1] = fmaf(r10, x, fmaf(r11, y, fmaf(r12, z, c1)));
        oa[3 * k + 2] = fmaf(r20, x, fmaf(r21, y, fmaf(r22, z, c2)));
    }

    float4* op = reinterpret_cast<float4*>(out + (size_t)b * 1536) + t * 3;
    op[0] = ov[0]; op[1] = ov[1]; op[2] = ov[2];
}

// ---------------------------------------------------------------------------
extern "C" void kernel_launch(void* const* d_in, const int* in_sizes, int n_in,
                              void* d_out, int out_size)
{
    const float* pred = (const float*)d_in[0];
    const float* truc = (const float*)d_in[1];
    const float* wgt  = (const float*)d_in[2];
    const unsigned int* msk = (const unsigned int*)d_in[3];
    float* out = (float*)d_out;

    k_fused<<<B_ / 2, 256>>>(pred, truc, wgt, msk, out);
}

// round 9
// speedup vs baseline: 1.3847x; 1.3174x over previous
#include <cuda_runtime.h>
#include <cstdint>
#include <cstddef>

#define B_ 8192
#define N_ 512

// fp32 cyclic Jacobi rotation on symmetric 3x3 (branchy: skips converged)
#define JROT(app, aqq, apq, arp, arq, vAp, vAq, vBp, vBq, vCp, vCq) do {      \
    float _a = (apq);                                                          \
    if (fabsf(_a) > 1e-12f * (fabsf(app) + fabsf(aqq))) {                      \
        float _th = 0.5f * ((aqq) - (app)) / _a;                               \
        float _t = copysignf(1.f, _th) / (fabsf(_th) + sqrtf(fmaf(_th, _th, 1.f))); \
        float _c = rsqrtf(fmaf(_t, _t, 1.f));                                  \
        float _s = _t * _c;                                                    \
        (app) -= _t * _a; (aqq) += _t * _a; (apq) = 0.f;                       \
        float _rp = (arp), _rq = (arq);                                        \
        (arp) = _c * _rp - _s * _rq; (arq) = _s * _rp + _c * _rq;              \
        float _x;                                                              \
        _x = (vAp); (vAp) = _c * _x - _s * (vAq); (vAq) = _s * _x + _c * (vAq);\
        _x = (vBp); (vBp) = _c * _x - _s * (vBq); (vBq) = _s * _x + _c * (vBq);\
        _x = (vCp); (vCp) = _c * _x - _s * (vCq); (vCq) = _s * _x + _c * (vCq);\
    } } while (0)

__device__ __forceinline__ float frsqrt(float x) {
    float y = rsqrtf(x);
    return y * (1.5f - (0.5f * x) * y * y);
}

// ---------------------------------------------------------------------------
// Fused: block = batch. Register-halving butterfly reduce (16 SHFL total),
// thread0 fp32 SVD, apply. true coords stay in registers across the SVD.
// ---------------------------------------------------------------------------
__global__ __launch_bounds__(128) void k_fused(
    const float* __restrict__ pred, const float* __restrict__ truc,
    const float* __restrict__ wgt, const unsigned int* __restrict__ msk,
    float* __restrict__ out)
{
    int b = blockIdx.x, tid = threadIdx.x;

    const float4* tp = reinterpret_cast<const float4*>(truc + (size_t)b * 1536) + tid * 3;
    const float4* pp = reinterpret_cast<const float4*>(pred + (size_t)b * 1536) + tid * 3;

    float4 tv0 = tp[0], tv1 = tp[1], tv2 = tp[2];
    float4 pv0 = pp[0], pv1 = pp[1], pv2 = pp[2];
    float4 wv4 = reinterpret_cast<const float4*>(wgt + (size_t)b * 512)[tid];
    uint4  mv  = reinterpret_cast<const uint4*>(msk + (size_t)b * 512)[tid];

    float ta[12] = { tv0.x, tv0.y, tv0.z, tv0.w, tv1.x, tv1.y, tv1.z, tv1.w,
                     tv2.x, tv2.y, tv2.z, tv2.w };
    float pa[12] = { pv0.x, pv0.y, pv0.z, pv0.w, pv1.x, pv1.y, pv1.z, pv1.w,
                     pv2.x, pv2.y, pv2.z, pv2.w };
    float wa[4]  = { wv4.x, wv4.y, wv4.z, wv4.w };
    unsigned int ma[4] = { mv.x, mv.y, mv.z, mv.w };

    float acc[16];
#pragma unroll
    for (int k = 0; k < 16; k++) acc[k] = 0.f;
    unsigned int m4 = 0;

#pragma unroll
    for (int k = 0; k < 4; k++) {
        unsigned int on = (ma[k] != 0u);
        m4 |= on << k;
        float w = on ? wa[k] : 0.f;
        float tx = ta[3 * k], ty = ta[3 * k + 1], tz = ta[3 * k + 2];
        float px = pa[3 * k], py = pa[3 * k + 1], pz = pa[3 * k + 2];
        float wtx = w * tx, wty = w * ty, wtz = w * tz;
        acc[0] = fmaf(wtx, px, acc[0]); acc[1] = fmaf(wtx, py, acc[1]); acc[2] = fmaf(wtx, pz, acc[2]);
        acc[3] = fmaf(wty, px, acc[3]); acc[4] = fmaf(wty, py, acc[4]); acc[5] = fmaf(wty, pz, acc[5]);
        acc[6] = fmaf(wtz, px, acc[6]); acc[7] = fmaf(wtz, py, acc[7]); acc[8] = fmaf(wtz, pz, acc[8]);
        acc[9] += wtx; acc[10] += wty; acc[11] += wtz;
        acc[12] = fmaf(w, px, acc[12]); acc[13] = fmaf(w, py, acc[13]); acc[14] = fmaf(w, pz, acc[14]);
        acc[15] += w;
    }

    // register-halving butterfly: 16 accs -> 1 per lane in 16 shuffles.
    // After all levels, even lane 2m holds the full-warp sum of acc index m.
    int lane = tid & 31, wid = tid >> 5;
#pragma unroll
    for (int i = 0; i < 8; i++) {
        bool hi = (lane & 16) != 0;
        float give = hi ? acc[i] : acc[i + 8];
        float keep = hi ? acc[i + 8] : acc[i];
        acc[i] = keep + __shfl_xor_sync(0xFFFFFFFFu, give, 16);
    }
#pragma unroll
    for (int i = 0; i < 4; i++) {
        bool hi = (lane & 8) != 0;
        float give = hi ? acc[i] : acc[i + 4];
        float keep = hi ? acc[i + 4] : acc[i];
        acc[i] = keep + __shfl_xor_sync(0xFFFFFFFFu, give, 8);
    }
#pragma unroll
    for (int i = 0; i < 2; i++) {
        bool hi = (lane & 4) != 0;
        float give = hi ? acc[i] : acc[i + 2];
        float keep = hi ? acc[i + 2] : acc[i];
        acc[i] = keep + __shfl_xor_sync(0xFFFFFFFFu, give, 4);
    }
    {
        bool hi = (lane & 2) != 0;
        float give = hi ? acc[0] : acc[1];
        float keep = hi ? acc[1] : acc[0];
        acc[0] = keep + __shfl_xor_sync(0xFFFFFFFFu, give, 2);
    }
    acc[0] += __shfl_xor_sync(0xFFFFFFFFu, acc[0], 1);

    __shared__ float sred[4][16];
    __shared__ float srt[12];
    if ((lane & 1) == 0)
        sred[wid][lane >> 1] = acc[0];
    __syncthreads();

    if (tid == 0) {
        float r[16];
#pragma unroll
        for (int k = 0; k < 16; k++)
            r[k] = sred[0][k] + sred[1][k] + sred[2][k] + sred[3][k];

        float inv = 1.f / r[15];
        float c0 = r[9] * inv, c1 = r[10] * inv, c2 = r[11] * inv;

        float cov[9];
#pragma unroll
        for (int i = 0; i < 3; i++)
#pragma unroll
            for (int j = 0; j < 3; j++)
                cov[i * 3 + j] = r[i * 3 + j] - r[9 + i] * r[12 + j] * inv;

        // M = cov^T cov (symmetric)
        float m00 = 0, m01 = 0, m02 = 0, m11 = 0, m12 = 0, m22 = 0;
#pragma unroll
        for (int k = 0; k < 3; k++) {
            float a0 = cov[k * 3], a1 = cov[k * 3 + 1], a2 = cov[k * 3 + 2];
            m00 = fmaf(a0, a0, m00); m01 = fmaf(a0, a1, m01); m02 = fmaf(a0, a2, m02);
            m11 = fmaf(a1, a1, m11); m12 = fmaf(a1, a2, m12); m22 = fmaf(a2, a2, m22);
        }

        float v00 = 1, v01 = 0, v02 = 0, v10 = 0, v11 = 1, v12 = 0, v20 = 0, v21 = 0, v22 = 1;
#pragma unroll
        for (int sweep = 0; sweep < 5; sweep++) {
            JROT(m00, m11, m01, m02, m12, v00, v01, v10, v11, v20, v21);
            JROT(m00, m22, m02, m01, m12, v00, v02, v10, v12, v20, v22);
            JROT(m11, m22, m12, m01, m02, v01, v02, v11, v12, v21, v22);
        }

        int imin = 0; float lmin = m00;
        if (m11 < lmin) { lmin = m11; imin = 1; }
        if (m22 < lmin) { lmin = m22; imin = 2; }
        int ia = (imin == 0) ? 1 : 0;
        int ib = (imin == 2) ? 1 : 2;

        float vd[9] = { v00, v01, v02, v10, v11, v12, v20, v21, v22 }; // col = eigvec

        // rebuild smallest-sigma direction as cross of the dominant two
        {
            float ax = vd[ia], ay = vd[3 + ia], az = vd[6 + ia];
            float bx = vd[ib], by = vd[3 + ib], bz = vd[6 + ib];
            float cx = ay * bz - az * by;
            float cy = az * bx - ax * bz;
            float cz = ax * by - ay * bx;
            float inm = frsqrt(cx * cx + cy * cy + cz * cz);
            vd[imin] = cx * inm; vd[3 + imin] = cy * inm; vd[6 + imin] = cz * inm;
        }

        // det sign (fp64, short chain)
        double det = (double)cov[0] * ((double)cov[4] * cov[8] - (double)cov[5] * cov[7])
                   - (double)cov[1] * ((double)cov[3] * cov[8] - (double)cov[5] * cov[6])
                   + (double)cov[2] * ((double)cov[3] * cov[7] - (double)cov[4] * cov[6]);

        float rot[9] = { 0, 0, 0, 0, 0, 0, 0, 0, 0 };
#pragma unroll
        for (int i = 0; i < 3; i++) {
            float vx = vd[i], vy = vd[3 + i], vz = vd[6 + i];
            float g0 = cov[0] * vx + cov[1] * vy + cov[2] * vz;
            float g1 = cov[3] * vx + cov[4] * vy + cov[5] * vz;
            float g2 = cov[6] * vx + cov[7] * vy + cov[8] * vz;
            float coef = frsqrt(fmaf(g0, g0, fmaf(g1, g1, g2 * g2)));
            if (i == imin && det < 0.0) coef = -coef;
            rot[0] = fmaf(coef * vx, g0, rot[0]); rot[1] = fmaf(coef * vx, g1, rot[1]); rot[2] = fmaf(coef * vx, g2, rot[2]);
            rot[3] = fmaf(coef * vy, g0, rot[3]); rot[4] = fmaf(coef * vy, g1, rot[4]); rot[5] = fmaf(coef * vy, g2, rot[5]);
            rot[6] = fmaf(coef * vz, g0, rot[6]); rot[7] = fmaf(coef * vz, g1, rot[7]); rot[8] = fmaf(coef * vz, g2, rot[8]);
        }

#pragma unroll
        for (int k = 0; k < 9; k++) srt[k] = rot[k];
        srt[9] = c0; srt[10] = c1; srt[11] = c2;
    }
    __syncthreads();

    float r00 = srt[0], r01 = srt[1], r02 = srt[2];
    float r10 = srt[3], r11 = srt[4], r12 = srt[5];
    float r20 = srt[6], r21 = srt[7], r22 = srt[8];
    float c0 = srt[9], c1 = srt[10], c2 = srt[11];

    float4 ov[3];
    float* oa = reinterpret_cast<float*>(ov);
#pragma unroll
    for (int k = 0; k < 4; k++) {
        float m = (m4 >> k) & 1u ? 1.f : 0.f;
        float x = ta[3 * k] * m - c0;
        float y = ta[3 * k + 1] * m - c1;
        float z = ta[3 * k + 2] * m - c2;
        oa[3 * k + 0] = fmaf(r00, x, fmaf(r01, y, fmaf(r02, z, c0)));
        oa[3 * k + 1] = fmaf(r10, x, fmaf(r11, y, fmaf(r12, z, c1)));
        oa[3 * k + 2] = fmaf(r20, x, fmaf(r21, y, fmaf(r22, z, c2)));
    }

    float4* op = reinterpret_cast<float4*>(out + (size_t)b * 1536) + tid * 3;
    op[0] = ov[0]; op[1] = ov[1]; op[2] = ov[2];
}

// ---------------------------------------------------------------------------
extern "C" void kernel_launch(void* const* d_in, const int* in_sizes, int n_in,
                              void* d_out, int out_size)
{
    const float* pred = (const float*)d_in[0];
    const float* truc = (const float*)d_in[1];
    const float* wgt  = (const float*)d_in[2];
    const unsigned int* msk = (const unsigned int*)d_in[3];
    float* out = (float*)d_out;

    k_fused<<<B_, 128>>>(pred, truc, wgt, msk, out);
}